// round 6
// baseline (speedup 1.0000x reference)
#include <cuda_runtime.h>
#include <cuda_bf16.h>
#include <math.h>
#include <stdint.h>

#define T_LEN 131072
#define NS 64
#define MD 8
#define NCH1 888          // 6 chunks per SM * 148
#define NCH3 148          // after 6-chain combine
#define L_BASE 147        // 131071 = 888*147 + 535
#define L_REM 535         // first 535 chunks have length 148

// ---- static device scratch ----
__device__ float g_w[(size_t)T_LEN * NS];
__device__ float g_maxlog[T_LEN];
__device__ float g_loglam[NS * MD];
__device__ float g_lamsum[NS];
__device__ float g_Alin[NS * NS];
__device__ float g_M1[(size_t)NCH1 * NS * NS];   // natural layout: [c][i][j]
__device__ float g_M3[(size_t)NCH3 * NS * NS];   // P-layout: [c][j][i] = R[i][j]
__device__ float g_S1[NCH1];
__device__ float g_S3[NCH3];
__device__ unsigned int g_hist[32];

// ================= helpers =================
__device__ __forceinline__ uint32_t smem_u32(const void* p) {
    uint32_t a;
    asm("{ .reg .u64 t; cvta.to.shared.u64 t, %1; cvt.u32.u64 %0, t; }" : "=r"(a) : "l"(p));
    return a;
}
#define SW128(o) ((uint32_t)(o) ^ ((((uint32_t)(o)) >> 3) & 0x70u))
#define CVT_BF2(r, lo, hi) asm("cvt.rn.bf16x2.f32 %0, %1, %2;" : "=r"(r) : "f"(hi), "f"(lo))
#define STS32(v, a) asm volatile("st.shared.b32 [%0], %1;" :: "r"(a), "r"(v) : "memory")
#define BAR_PAIR(id) asm volatile("bar.sync %0, 64;" :: "r"(id) : "memory")
#define LDSM_X4(r0, r1, r2, r3, a) \
    asm volatile("ldmatrix.sync.aligned.m8n8.x4.shared.b16 {%0,%1,%2,%3}, [%4];" \
                 : "=r"(r0), "=r"(r1), "=r"(r2), "=r"(r3) : "r"(a))
#define LDSM_X4_T(r0, r1, r2, r3, a) \
    asm volatile("ldmatrix.sync.aligned.m8n8.x4.trans.shared.b16 {%0,%1,%2,%3}, [%4];" \
                 : "=r"(r0), "=r"(r1), "=r"(r2), "=r"(r3) : "r"(a))
#define MMA_BF16(d, a, b0, b1) \
    asm volatile("mma.sync.aligned.m16n8k16.row.col.f32.bf16.bf16.f32 " \
                 "{%0,%1,%2,%3}, {%4,%5,%6,%7}, {%8,%9}, {%0,%1,%2,%3};" \
                 : "+f"((d)[0]), "+f"((d)[1]), "+f"((d)[2]), "+f"((d)[3]) \
                 : "r"((a)[0]), "r"((a)[1]), "r"((a)[2]), "r"((a)[3]), "r"(b0), "r"(b1))

__device__ __forceinline__ int chunk_t0(int c) { return 1 + c * L_BASE + (c < L_REM ? c : L_REM); }
__device__ __forceinline__ int chunk_len(int c) { return L_BASE + (c < L_REM ? 1 : 0); }

// ============================================================
__global__ void setup_kernel(const float* __restrict__ lambdas,
                             const float* __restrict__ log_transition) {
    int tid = threadIdx.x;
    for (int idx = tid; idx < NS * MD; idx += blockDim.x)
        g_loglam[idx] = logf(lambdas[idx]);
    if (tid < NS) {
        float s = 0.f;
        #pragma unroll
        for (int m = 0; m < MD; m++) s += lambdas[tid * MD + m];
        g_lamsum[tid] = s;
    }
    for (int idx = tid; idx < NS * NS; idx += blockDim.x)
        g_Alin[idx] = expf(log_transition[idx]);
    if (tid < 32) g_hist[tid] = 0u;
}

// ============================================================
__global__ void __launch_bounds__(256) pass0_kernel(const int* __restrict__ x) {
    __shared__ float sll[NS * MD];
    __shared__ float slam[NS];
    __shared__ unsigned int shist[32];
    int tid = threadIdx.x;
    for (int idx = tid; idx < NS * MD; idx += blockDim.x) sll[idx] = g_loglam[idx];
    if (tid < NS) slam[tid] = g_lamsum[tid];
    if (tid < 32) shist[tid] = 0u;
    __syncthreads();

    int warp = tid >> 5, lane = tid & 31;
    int t = blockIdx.x * 8 + warp;

    int4 xa = *(const int4*)&x[(size_t)t * MD];
    int4 xb = *(const int4*)&x[(size_t)t * MD + 4];
    int xv[8] = {xa.x, xa.y, xa.z, xa.w, xb.x, xb.y, xb.z, xb.w};
    if (lane < 8) atomicAdd(&shist[xv[lane] & 31], 1u);

    float e0 = -slam[lane], e1 = -slam[lane + 32];
    #pragma unroll
    for (int m = 0; m < 8; m++) {
        float xm = (float)xv[m];
        e0 = fmaf(xm, sll[lane * MD + m], e0);
        e1 = fmaf(xm, sll[(lane + 32) * MD + m], e1);
    }
    float mx = fmaxf(e0, e1);
    #pragma unroll
    for (int o = 16; o > 0; o >>= 1)
        mx = fmaxf(mx, __shfl_xor_sync(0xffffffffu, mx, o));
    g_w[(size_t)t * NS + lane]      = expf(e0 - mx);
    g_w[(size_t)t * NS + lane + 32] = expf(e1 - mx);
    if (lane == 0) g_maxlog[t] = mx;

    __syncthreads();
    if (tid < 32 && shist[tid]) atomicAdd(&g_hist[tid], shist[tid]);
}

// ============================================================
// Pass 1: 128 threads = 2 independent chunk-groups of 2 warps each.
// Warp w of group g computes full m=64 x n=[32w,32w+32) of chunk 2*blk+g.
// Groups sync only via named barriers (bar.sync g+1, 64).
// Renorm every 8 steps + forced last step. Ping-pong M tiles.
// ============================================================
#define RENORM_MASK 7
__global__ void __launch_bounds__(128, 3) pass1_mma() {
    __shared__ __align__(1024) unsigned char sAraw[NS * 128];
    __shared__ __align__(1024) unsigned char sMraw[2][2][NS * 128];  // [group][pingpong]
    __shared__ float swf[2][2][NS];   // [group][buf][state]
    __shared__ float wmax[2][2];      // [group][warp]

    int tid = threadIdx.x, lane = tid & 31, wid = tid >> 5;
    int g = wid >> 1;                 // chunk group 0/1
    int w = wid & 1;                  // warp within group
    int ptid = tid & 63;              // thread within group

    int c = blockIdx.x * 2 + g;
    int t0 = chunk_t0(c);
    int nst = chunk_len(c);

    uint32_t sA = smem_u32(sAraw);
    uint32_t sMg = smem_u32(sMraw[g][0]);

    // A -> bf16 swizzled SMEM
    for (int idx = tid; idx < NS * NS; idx += 128) {
        int i = idx >> 6, k = idx & 63;
        *(__nv_bfloat16*)(sAraw + SW128(i * 128 + k * 2)) = __float2bfloat16(g_Alin[idx]);
    }
    // both groups' tile 0 = zero
    for (int idx = tid; idx < (2 * NS * 128) / 4; idx += 128) {
        int grp = idx >= (NS * 128) / 4;
        ((uint32_t*)sMraw[grp][0])[idx & ((NS * 128) / 4 - 1)] = 0u;
    }
    __syncthreads();
    {   // identity + first emission weights (tid 0..127 covers both groups x 64 states)
        int gg = tid >> 6, j = tid & 63;
        int cg = blockIdx.x * 2 + gg;
        *(__nv_bfloat16*)(sMraw[gg][0] + SW128(j * 128 + j * 2)) = __float2bfloat16(1.0f);
        swf[gg][0][j] = g_w[(size_t)chunk_t0(cg) * NS + j];
    }
    __syncthreads();

    // Register-resident A fragments: afr[mt][kt][0..3]
    uint32_t afr[4][4][4];
    {
        int gq = lane >> 3, r = lane & 7;
        #pragma unroll
        for (int mt = 0; mt < 4; mt++)
            #pragma unroll
            for (int kt = 0; kt < 4; kt++) {
                int row = mt * 16 + (gq & 1) * 8 + r;
                int col = kt * 16 + (gq >> 1) * 8;
                LDSM_X4(afr[mt][kt][0], afr[mt][kt][1], afr[mt][kt][2], afr[mt][kt][3],
                        sA + SW128(row * 128 + col * 2));
            }
    }
    // B ldmatrix addresses: warp w owns cols [32w, 32w+32); h = 16-col half
    uint32_t baddr[4][2];
    {
        int gq = lane >> 3, r = lane & 7;
        #pragma unroll
        for (int kt = 0; kt < 4; kt++)
            #pragma unroll
            for (int h = 0; h < 2; h++) {
                int row = kt * 16 + (gq & 1) * 8 + r;
                int col = w * 32 + h * 16 + (gq >> 1) * 8;
                baddr[kt][h] = sMg + SW128(row * 128 + col * 2);
            }
    }

    int r0b = lane >> 2;            // 0..7
    int cpair = (lane & 3) * 2;     // 0,2,4,6
    int barid = g + 1;
    float S = 0.f;

    for (int step = 0; step < nst; step++) {
        int cur = step & 1;
        uint32_t curoff = (uint32_t)cur << 13;   // 8192 per tile
        bool last = (step == nst - 1);
        bool renorm = ((step & RENORM_MASK) == RENORM_MASK) || last;

        float wn = 0.f;
        if (!last) wn = g_w[(size_t)(t0 + step + 1) * NS + ptid];
        float ml = (ptid == 0) ? g_maxlog[t0 + step] : 0.f;

        float acc[4][4][4];   // [mt][nt(n8)][elem]
        #pragma unroll
        for (int mt = 0; mt < 4; mt++)
            #pragma unroll
            for (int nt = 0; nt < 4; nt++)
                #pragma unroll
                for (int e = 0; e < 4; e++) acc[mt][nt][e] = 0.f;

        #pragma unroll
        for (int kt = 0; kt < 4; kt++) {
            #pragma unroll
            for (int h = 0; h < 2; h++) {
                uint32_t b0, b1, b2, b3;
                LDSM_X4_T(b0, b1, b2, b3, baddr[kt][h] + curoff);
                #pragma unroll
                for (int mt = 0; mt < 4; mt++) {
                    MMA_BF16(acc[mt][2 * h],     afr[mt][kt], b0, b1);
                    MMA_BF16(acc[mt][2 * h + 1], afr[mt][kt], b2, b3);
                }
            }
        }

        // scale rows by emission weights
        #pragma unroll
        for (int mt = 0; mt < 4; mt++) {
            float w0 = swf[g][cur][mt * 16 + r0b];
            float w1 = swf[g][cur][mt * 16 + 8 + r0b];
            #pragma unroll
            for (int nt = 0; nt < 4; nt++) {
                acc[mt][nt][0] *= w0; acc[mt][nt][1] *= w0;
                acc[mt][nt][2] *= w1; acc[mt][nt][3] *= w1;
            }
        }

        if (!last) {
            uint32_t dstb = sMg + (curoff ^ 8192u);
            #pragma unroll
            for (int mt = 0; mt < 4; mt++) {
                #pragma unroll
                for (int nt = 0; nt < 4; nt++) {
                    int col = w * 32 + nt * 8 + cpair;
                    uint32_t p0, p1;
                    CVT_BF2(p0, acc[mt][nt][0], acc[mt][nt][1]);
                    CVT_BF2(p1, acc[mt][nt][2], acc[mt][nt][3]);
                    STS32(p0, sMg + ((curoff ^ 8192u) - curoff + curoff) * 0 + (uint32_t)0 + SW128((mt * 16 + r0b) * 128 + col * 2) + (curoff ^ 8192u));
                    STS32(p1, SW128((mt * 16 + 8 + r0b) * 128 + col * 2) + dstb);
                    (void)dstb;
                }
            }
        }

        if (renorm) {
            float lmax = 0.f;
            #pragma unroll
            for (int mt = 0; mt < 4; mt++)
                #pragma unroll
                for (int nt = 0; nt < 4; nt++)
                    #pragma unroll
                    for (int e = 0; e < 4; e++) lmax = fmaxf(lmax, acc[mt][nt][e]);
            #pragma unroll
            for (int o = 16; o > 0; o >>= 1)
                lmax = fmaxf(lmax, __shfl_xor_sync(0xffffffffu, lmax, o));
            if (lane == 0) wmax[g][w] = lmax;
            BAR_PAIR(barid);
            float s = fmaxf(fmaxf(wmax[g][0], wmax[g][1]), 1e-30f);
            float inv = 1.0f / s;
            if (!last) {
                swf[g][cur ^ 1][ptid] = wn * inv;
                if (ptid == 0) S += ml + __logf(s);
            } else {
                float* gd = g_M1 + (size_t)c * (NS * NS);
                #pragma unroll
                for (int mt = 0; mt < 4; mt++) {
                    #pragma unroll
                    for (int nt = 0; nt < 4; nt++) {
                        int col = w * 32 + nt * 8 + cpair;
                        *(float2*)&gd[(mt * 16 + r0b) * NS + col] =
                            make_float2(acc[mt][nt][0] * inv, acc[mt][nt][1] * inv);
                        *(float2*)&gd[(mt * 16 + 8 + r0b) * NS + col] =
                            make_float2(acc[mt][nt][2] * inv, acc[mt][nt][3] * inv);
                    }
                }
                if (ptid == 0) S += ml + __logf(s);
            }
        } else {
            swf[g][cur ^ 1][ptid] = wn;
            if (ptid == 0) S += ml;
        }
        BAR_PAIR(barid);   // new M tile + swf visible within the pair
    }
    if (ptid == 0) g_S1[c] = S;
}

// ============================================================
// 6-chain combine: R = M[6c+5] @ ... @ M[6c]; store R in P-layout.
// Running product T in sY; each phase loads next M^T into sX.
// ============================================================
#define CPAD 68
__global__ void __launch_bounds__(256) combine6_kernel() {
    __shared__ float sX[NS * CPAD];
    __shared__ float sY[NS * CPAD];
    int c = blockIdx.x, tid = threadIdx.x;
    const float* M = g_M1 + (size_t)(6 * c) * NS * NS;

    // T = M0 (direct [k][j])
    for (int idx = tid; idx < NS * NS; idx += 256)
        sY[(idx >> 6) * CPAD + (idx & 63)] = M[idx];

    int x0 = (tid >> 4) << 2;
    int y0 = (tid & 15) << 2;
    float acc[4][4];

    #pragma unroll 1
    for (int ph = 1; ph <= 4; ph++) {
        const float* Mn = M + (size_t)ph * NS * NS;
        for (int idx = tid; idx < NS * NS; idx += 256)
            sX[(idx & 63) * CPAD + (idx >> 6)] = Mn[idx];   // Mn^T: sX[k][i]
        __syncthreads();
        #pragma unroll
        for (int a = 0; a < 4; a++)
            #pragma unroll
            for (int b = 0; b < 4; b++) acc[a][b] = 0.f;
        #pragma unroll 8
        for (int k = 0; k < NS; k++) {
            float4 av = *(const float4*)&sX[k * CPAD + x0];
            float4 bv = *(const float4*)&sY[k * CPAD + y0];
            float aa[4] = {av.x, av.y, av.z, av.w};
            float bb[4] = {bv.x, bv.y, bv.z, bv.w};
            #pragma unroll
            for (int a = 0; a < 4; a++)
                #pragma unroll
                for (int b = 0; b < 4; b++)
                    acc[a][b] = fmaf(aa[a], bb[b], acc[a][b]);
        }
        __syncthreads();
        #pragma unroll
        for (int a = 0; a < 4; a++)
            *(float4*)&sY[(x0 + a) * CPAD + y0] =
                make_float4(acc[a][0], acc[a][1], acc[a][2], acc[a][3]);
    }

    // final phase with M5: R^T[j][i] = sum_k T[k][j] * M5[i][k]
    {
        const float* Mn = M + (size_t)5 * NS * NS;
        for (int idx = tid; idx < NS * NS; idx += 256)
            sX[(idx & 63) * CPAD + (idx >> 6)] = Mn[idx];
        __syncthreads();
        #pragma unroll
        for (int a = 0; a < 4; a++)
            #pragma unroll
            for (int b = 0; b < 4; b++) acc[a][b] = 0.f;
        #pragma unroll 8
        for (int k = 0; k < NS; k++) {
            float4 av = *(const float4*)&sY[k * CPAD + x0];   // T[k][j]
            float4 bv = *(const float4*)&sX[k * CPAD + y0];   // M5^T[k][i]
            float aa[4] = {av.x, av.y, av.z, av.w};
            float bb[4] = {bv.x, bv.y, bv.z, bv.w};
            #pragma unroll
            for (int a = 0; a < 4; a++)
                #pragma unroll
                for (int b = 0; b < 4; b++)
                    acc[a][b] = fmaf(aa[a], bb[b], acc[a][b]);
        }
        float* dst = g_M3 + (size_t)c * NS * NS;   // P-layout [j][i]
        #pragma unroll
        for (int a = 0; a < 4; a++)
            *(float4*)&dst[(x0 + a) * NS + y0] =
                make_float4(acc[a][0], acc[a][1], acc[a][2], acc[a][3]);
    }
    if (tid == 0) {
        float s = 0.f;
        #pragma unroll
        for (int q = 0; q < 6; q++) s += g_S1[6 * c + q];
        g_S3[c] = s;
    }
}

// ============================================================
// Pass 2: serial matvec over 148 combined chunks (P-layout).
// ============================================================
__global__ void __launch_bounds__(256) pass2_kernel(const int* __restrict__ x,
                                                    const float* __restrict__ priors,
                                                    float* __restrict__ out) {
    __shared__ float alpha[NS];
    __shared__ float part[256];
    __shared__ float anew[NS];
    __shared__ float evec[NS];
    __shared__ float wm2[2];
    int tid = threadIdx.x;
    int i = tid & 63, q = tid >> 6;

    if (tid < NS) {
        float e = priors[tid] - g_lamsum[tid];
        #pragma unroll
        for (int m = 0; m < MD; m++)
            e = fmaf((float)x[m], g_loglam[tid * MD + m], e);
        evec[tid] = e;
    }
    __syncthreads();
    if (tid < NS) {
        float m = evec[tid];
        #pragma unroll
        for (int o = 16; o > 0; o >>= 1)
            m = fmaxf(m, __shfl_xor_sync(0xffffffffu, m, o));
        if ((tid & 31) == 0) wm2[tid >> 5] = m;
    }
    __syncthreads();
    float m0 = fmaxf(wm2[0], wm2[1]);
    if (tid < NS) alpha[tid] = expf(evec[tid] - m0);
    double logscale = (double)m0;
    __syncthreads();

    float buf[2][16];
    #pragma unroll
    for (int r = 0; r < 16; r++)
        buf[0][r] = g_M3[(size_t)(q * 16 + r) * NS + i];
    int pp = 0;
    for (int c = 0; c < NCH3; c++) {
        if (c + 1 < NCH3) {
            #pragma unroll
            for (int r = 0; r < 16; r++)
                buf[pp ^ 1][r] = g_M3[(size_t)(c + 1) * (NS * NS) + (size_t)(q * 16 + r) * NS + i];
        }
        float partial = 0.f;
        #pragma unroll
        for (int r = 0; r < 16; r++)
            partial = fmaf(buf[pp][r], alpha[q * 16 + r], partial);
        part[tid] = partial;
        __syncthreads();
        if (tid < NS) {
            float a4 = part[tid] + part[tid + 64] + part[tid + 128] + part[tid + 192];
            anew[tid] = a4;
            float m = a4;
            #pragma unroll
            for (int o = 16; o > 0; o >>= 1)
                m = fmaxf(m, __shfl_xor_sync(0xffffffffu, m, o));
            if ((tid & 31) == 0) wm2[tid >> 5] = m;
        }
        __syncthreads();
        float s = fmaxf(fmaxf(wm2[0], wm2[1]), 1e-35f);
        if (tid == 0) logscale += (double)g_S3[c] + log((double)s);
        if (tid < NS) alpha[tid] = anew[tid] / s;
        __syncthreads();
        pp ^= 1;
    }

    if (tid == 0) {
        double sum = 0.0;
        for (int k = 0; k < NS; k++) sum += (double)alpha[k];
        double lgam = 0.0;
        for (int b = 0; b < 32; b++) {
            unsigned int cnt = g_hist[b];
            if (cnt) lgam += (double)cnt * lgamma((double)b + 1.0);
        }
        out[0] = (float)(logscale + log(sum) - lgam);
    }
}

// ============================================================
extern "C" void kernel_launch(void* const* d_in, const int* in_sizes, int n_in,
                              void* d_out, int out_size) {
    const int*   x              = (const int*)d_in[0];
    const float* lambdas        = (const float*)d_in[1];
    const float* log_transition = (const float*)d_in[2];
    const float* priors         = (const float*)d_in[3];
    float* out = (float*)d_out;

    setup_kernel<<<1, 256>>>(lambdas, log_transition);
    pass0_kernel<<<T_LEN / 8, 256>>>(x);
    pass1_mma<<<NCH1 / 2, 128>>>();
    combine6_kernel<<<NCH3, 256>>>();
    pass2_kernel<<<1, 256>>>(x, priors, out);
}

// round 7
// speedup vs baseline: 1.1303x; 1.1303x over previous
#include <cuda_runtime.h>
#include <cuda_bf16.h>
#include <math.h>
#include <stdint.h>

#define T_LEN 131072
#define NS 64
#define MD 8
#define NCH1 444          // pass1 chunks: 3 per SM * 148
#define NCH3 148          // after triple-combine
#define L_BASE 295        // 131071 = 444*295 + 91
#define L_REM 91          // first 91 chunks have length 296

// ---- static device scratch ----
__device__ float g_wf[(size_t)T_LEN * NS];    // fragment-ordered weights: [t][r*8+k] = w[t][k*8+r]
__device__ float g_maxlog[T_LEN];
__device__ float g_loglam[NS * MD];
__device__ float g_lamsum[NS];
__device__ float g_Alin[NS * NS];
__device__ float g_M1[(size_t)NCH1 * NS * NS];   // natural layout: [c][i][j]
__device__ float g_M3[(size_t)NCH3 * NS * NS];   // P-layout: [c][j][i] = R[i][j]
__device__ float g_S1[NCH1];
__device__ float g_S3[NCH3];
__device__ unsigned int g_hist[32];

// ================= helpers =================
__device__ __forceinline__ uint32_t smem_u32(const void* p) {
    uint32_t a;
    asm("{ .reg .u64 t; cvta.to.shared.u64 t, %1; cvt.u32.u64 %0, t; }" : "=r"(a) : "l"(p));
    return a;
}
#define SW128(o) ((uint32_t)(o) ^ ((((uint32_t)(o)) >> 3) & 0x70u))
#define CVT_BF2(r, lo, hi) asm("cvt.rn.bf16x2.f32 %0, %1, %2;" : "=r"(r) : "f"(hi), "f"(lo))
#define STS32(v, a) asm volatile("st.shared.b32 [%0], %1;" :: "r"(a), "r"(v) : "memory")
#define LDSM_X4(r0, r1, r2, r3, a) \
    asm volatile("ldmatrix.sync.aligned.m8n8.x4.shared.b16 {%0,%1,%2,%3}, [%4];" \
                 : "=r"(r0), "=r"(r1), "=r"(r2), "=r"(r3) : "r"(a))
#define LDSM_X4_T(r0, r1, r2, r3, a) \
    asm volatile("ldmatrix.sync.aligned.m8n8.x4.trans.shared.b16 {%0,%1,%2,%3}, [%4];" \
                 : "=r"(r0), "=r"(r1), "=r"(r2), "=r"(r3) : "r"(a))
#define MMA_BF16(d, a, b0, b1) \
    asm volatile("mma.sync.aligned.m16n8k16.row.col.f32.bf16.bf16.f32 " \
                 "{%0,%1,%2,%3}, {%4,%5,%6,%7}, {%8,%9}, {%0,%1,%2,%3};" \
                 : "+f"((d)[0]), "+f"((d)[1]), "+f"((d)[2]), "+f"((d)[3]) \
                 : "r"((a)[0]), "r"((a)[1]), "r"((a)[2]), "r"((a)[3]), "r"(b0), "r"(b1))

__device__ __forceinline__ int chunk_t0(int c) { return 1 + c * L_BASE + (c < L_REM ? c : L_REM); }
__device__ __forceinline__ int chunk_len(int c) { return L_BASE + (c < L_REM ? 1 : 0); }

// ============================================================
__global__ void setup_kernel(const float* __restrict__ lambdas,
                             const float* __restrict__ log_transition) {
    int tid = threadIdx.x;
    for (int idx = tid; idx < NS * MD; idx += blockDim.x)
        g_loglam[idx] = logf(lambdas[idx]);
    if (tid < NS) {
        float s = 0.f;
        #pragma unroll
        for (int m = 0; m < MD; m++) s += lambdas[tid * MD + m];
        g_lamsum[tid] = s;
    }
    for (int idx = tid; idx < NS * NS; idx += blockDim.x)
        g_Alin[idx] = expf(log_transition[idx]);
    if (tid < 32) g_hist[tid] = 0u;
}

// ============================================================
__global__ void __launch_bounds__(256) pass0_kernel(const int* __restrict__ x) {
    __shared__ float sll[NS * MD];
    __shared__ float slam[NS];
    __shared__ unsigned int shist[32];
    int tid = threadIdx.x;
    for (int idx = tid; idx < NS * MD; idx += blockDim.x) sll[idx] = g_loglam[idx];
    if (tid < NS) slam[tid] = g_lamsum[tid];
    if (tid < 32) shist[tid] = 0u;
    __syncthreads();

    int warp = tid >> 5, lane = tid & 31;
    int t = blockIdx.x * 8 + warp;

    int4 xa = *(const int4*)&x[(size_t)t * MD];
    int4 xb = *(const int4*)&x[(size_t)t * MD + 4];
    int xv[8] = {xa.x, xa.y, xa.z, xa.w, xb.x, xb.y, xb.z, xb.w};
    if (lane < 8) atomicAdd(&shist[xv[lane] & 31], 1u);

    float e0 = -slam[lane], e1 = -slam[lane + 32];
    #pragma unroll
    for (int m = 0; m < 8; m++) {
        float xm = (float)xv[m];
        e0 = fmaf(xm, sll[lane * MD + m], e0);
        e1 = fmaf(xm, sll[(lane + 32) * MD + m], e1);
    }
    float mx = fmaxf(e0, e1);
    #pragma unroll
    for (int o = 16; o > 0; o >>= 1)
        mx = fmaxf(mx, __shfl_xor_sync(0xffffffffu, mx, o));
    // fragment-ordered store: state s -> slot (s&7)*8 + (s>>3)
    g_wf[(size_t)t * NS + (lane & 7) * 8 + (lane >> 3)]     = expf(e0 - mx);
    g_wf[(size_t)t * NS + (lane & 7) * 8 + (lane >> 3) + 4] = expf(e1 - mx);
    if (lane == 0) g_maxlog[t] = mx;

    __syncthreads();
    if (tid < 32 && shist[tid]) atomicAdd(&g_hist[tid], shist[tid]);
}

// ============================================================
// Pass 1: one 64x64 chunk per CTA, 4 warps, WARP-AUTONOMOUS steps.
// Warp w owns output cols [16w,16w+16) = its own B operand next step,
// so normal steps need NO cta barrier (only __syncwarp for STS->LDSM).
// Renorm every 8 steps (+last): the only cross-warp sync.
// ============================================================
#define RENORM_MASK 7
__global__ void __launch_bounds__(128, 3) pass1_mma() {
    __shared__ __align__(1024) unsigned char sAraw[NS * 128];
    __shared__ __align__(1024) unsigned char sMraw[NS * 128];
    __shared__ float wmax[2][4];   // [renorm parity][warp]

    int tid = threadIdx.x, lane = tid & 31, wid = tid >> 5;
    int c = blockIdx.x;
    int t0 = chunk_t0(c);
    int nst = chunk_len(c);

    uint32_t sA = smem_u32(sAraw), sM = smem_u32(sMraw);

    // A -> bf16 swizzled SMEM
    for (int idx = tid; idx < NS * NS; idx += 128) {
        int i = idx >> 6, k = idx & 63;
        *(__nv_bfloat16*)(sAraw + SW128(i * 128 + k * 2)) = __float2bfloat16(g_Alin[idx]);
    }
    // M = identity
    for (int idx = tid; idx < (NS * 128) / 4; idx += 128)
        ((uint32_t*)sMraw)[idx] = 0u;
    __syncthreads();
    if (tid < NS)
        *(__nv_bfloat16*)(sMraw + SW128(tid * 128 + tid * 2)) = __float2bfloat16(1.0f);
    __syncthreads();

    // Register-resident A fragments
    uint32_t afr[4][4][4];
    {
        int g = lane >> 3, r = lane & 7;
        #pragma unroll
        for (int mt = 0; mt < 4; mt++)
            #pragma unroll
            for (int kt = 0; kt < 4; kt++) {
                int row = mt * 16 + (g & 1) * 8 + r;
                int col = kt * 16 + (g >> 1) * 8;
                LDSM_X4(afr[mt][kt][0], afr[mt][kt][1], afr[mt][kt][2], afr[mt][kt][3],
                        sA + SW128(row * 128 + col * 2));
            }
    }
    // B ldmatrix addresses (warp's own 16-col block; single buffer)
    uint32_t baddr[4];
    {
        int g = lane >> 3, r = lane & 7;
        #pragma unroll
        for (int kt = 0; kt < 4; kt++) {
            int row = kt * 16 + (g & 1) * 8 + r;
            int col = wid * 16 + (g >> 1) * 8;
            baddr[kt] = sM + SW128(row * 128 + col * 2);
        }
    }

    int r0b = lane >> 2;            // 0..7
    int cpair = (lane & 3) * 2;     // 0,2,4,6
    float S = 0.f;
    float invp = 1.0f;              // pending renorm inverse (per-warp scalar)

    for (int step = 0; step < nst; step++) {
        bool last = (step == nst - 1);
        bool renorm = ((step & RENORM_MASK) == RENORM_MASK) || last;
        int t = t0 + step;

        // weights for this step, fragment-ordered: 2x LDG.128, 4-lane broadcast
        const float4* wp = (const float4*)&g_wf[(size_t)t * NS + r0b * 8];
        float4 wa = wp[0];
        float4 wb = wp[1];
        float ml = (tid == 0) ? g_maxlog[t] : 0.f;

        float acc[4][2][4];
        #pragma unroll
        for (int mt = 0; mt < 4; mt++)
            #pragma unroll
            for (int nt = 0; nt < 2; nt++)
                #pragma unroll
                for (int e = 0; e < 4; e++) acc[mt][nt][e] = 0.f;

        #pragma unroll
        for (int kt = 0; kt < 4; kt++) {
            uint32_t b0, b1, b2, b3;
            LDSM_X4_T(b0, b1, b2, b3, baddr[kt]);
            #pragma unroll
            for (int mt = 0; mt < 4; mt++) {
                MMA_BF16(acc[mt][0], afr[mt][kt], b0, b1);
                MMA_BF16(acc[mt][1], afr[mt][kt], b2, b3);
            }
        }

        // fold pending inverse into weights, then scale rows
        wa.x *= invp; wa.y *= invp; wa.z *= invp; wa.w *= invp;
        wb.x *= invp; wb.y *= invp; wb.z *= invp; wb.w *= invp;
        float wlo[4] = {wa.x, wa.z, wb.x, wb.z};   // rows mt*16+r0b
        float whi[4] = {wa.y, wa.w, wb.y, wb.w};   // rows mt*16+8+r0b
        #pragma unroll
        for (int mt = 0; mt < 4; mt++) {
            #pragma unroll
            for (int nt = 0; nt < 2; nt++) {
                acc[mt][nt][0] *= wlo[mt]; acc[mt][nt][1] *= wlo[mt];
                acc[mt][nt][2] *= whi[mt]; acc[mt][nt][3] *= whi[mt];
            }
        }

        if (!last) {
            // write back to own col block (in-warp WAR: LDSM data already in regs)
            #pragma unroll
            for (int mt = 0; mt < 4; mt++) {
                #pragma unroll
                for (int nt = 0; nt < 2; nt++) {
                    int col = wid * 16 + nt * 8 + cpair;
                    uint32_t p0, p1;
                    CVT_BF2(p0, acc[mt][nt][0], acc[mt][nt][1]);
                    CVT_BF2(p1, acc[mt][nt][2], acc[mt][nt][3]);
                    STS32(p0, sM + SW128((mt * 16 + r0b) * 128 + col * 2));
                    STS32(p1, sM + SW128((mt * 16 + 8 + r0b) * 128 + col * 2));
                }
            }
        }

        if (renorm) {
            float lmax = 0.f;
            #pragma unroll
            for (int mt = 0; mt < 4; mt++)
                #pragma unroll
                for (int nt = 0; nt < 2; nt++)
                    #pragma unroll
                    for (int e = 0; e < 4; e++) lmax = fmaxf(lmax, acc[mt][nt][e]);
            #pragma unroll
            for (int o = 16; o > 0; o >>= 1)
                lmax = fmaxf(lmax, __shfl_xor_sync(0xffffffffu, lmax, o));
            int par = (step >> 3) & 1;
            if (lane == 0) wmax[par][wid] = lmax;
            __syncthreads();   // only cross-warp sync: 1 in 8 steps
            float s = fmaxf(fmaxf(fmaxf(wmax[par][0], wmax[par][1]),
                                  fmaxf(wmax[par][2], wmax[par][3])), 1e-30f);
            invp = 1.0f / s;
            if (tid == 0) S += ml + __logf(s);
            if (last) {
                float* gd = g_M1 + (size_t)c * (NS * NS);
                #pragma unroll
                for (int mt = 0; mt < 4; mt++) {
                    #pragma unroll
                    for (int nt = 0; nt < 2; nt++) {
                        int col = wid * 16 + nt * 8 + cpair;
                        *(float2*)&gd[(mt * 16 + r0b) * NS + col] =
                            make_float2(acc[mt][nt][0] * invp, acc[mt][nt][1] * invp);
                        *(float2*)&gd[(mt * 16 + 8 + r0b) * NS + col] =
                            make_float2(acc[mt][nt][2] * invp, acc[mt][nt][3] * invp);
                    }
                }
            }
        } else {
            invp = 1.0f;
            if (tid == 0) S += ml;
        }
        __syncwarp(0xffffffffu);   // STS visible to whole warp before next LDSM
    }
    if (tid == 0) g_S1[c] = S;
}

// ============================================================
// Triple-combine: R = M[3c+2] @ M[3c+1] @ M[3c]; store R in P-layout.
// ============================================================
#define CPAD 68
__global__ void __launch_bounds__(256) combine3_kernel() {
    __shared__ float sX[NS * CPAD];
    __shared__ float sY[NS * CPAD];
    int c = blockIdx.x, tid = threadIdx.x;
    const float* Ma = g_M1 + (size_t)(3 * c) * NS * NS;
    const float* Mb = Ma + NS * NS;
    const float* Mc = Mb + NS * NS;

    for (int idx = tid; idx < NS * NS; idx += 256) {
        int i = idx >> 6, k = idx & 63;
        sX[k * CPAD + i] = Mb[idx];    // Mb^T
        sY[i * CPAD + k] = Ma[idx];    // Ma direct [row=k-dim][col=j]
    }
    __syncthreads();

    int x0 = (tid >> 4) << 2;
    int y0 = (tid & 15) << 2;
    float acc[4][4];

    // ---- phase 1: T = Mb @ Ma ----
    #pragma unroll
    for (int a = 0; a < 4; a++)
        #pragma unroll
        for (int b = 0; b < 4; b++) acc[a][b] = 0.f;
    #pragma unroll 8
    for (int k = 0; k < NS; k++) {
        float4 av = *(const float4*)&sX[k * CPAD + x0];
        float4 bv = *(const float4*)&sY[k * CPAD + y0];
        float aa[4] = {av.x, av.y, av.z, av.w};
        float bb[4] = {bv.x, bv.y, bv.z, bv.w};
        #pragma unroll
        for (int a = 0; a < 4; a++)
            #pragma unroll
            for (int b = 0; b < 4; b++)
                acc[a][b] = fmaf(aa[a], bb[b], acc[a][b]);
    }
    __syncthreads();

    // T -> sY; Mc^T -> sX
    #pragma unroll
    for (int a = 0; a < 4; a++)
        *(float4*)&sY[(x0 + a) * CPAD + y0] =
            make_float4(acc[a][0], acc[a][1], acc[a][2], acc[a][3]);
    for (int idx = tid; idx < NS * NS; idx += 256) {
        int i = idx >> 6, k = idx & 63;
        sX[k * CPAD + i] = Mc[idx];
    }
    __syncthreads();

    // ---- phase 2: R^T[j][i] = sum_k T[k][j] * Mc[i][k] ----
    #pragma unroll
    for (int a = 0; a < 4; a++)
        #pragma unroll
        for (int b = 0; b < 4; b++) acc[a][b] = 0.f;
    #pragma unroll 8
    for (int k = 0; k < NS; k++) {
        float4 av = *(const float4*)&sY[k * CPAD + x0];
        float4 bv = *(const float4*)&sX[k * CPAD + y0];
        float aa[4] = {av.x, av.y, av.z, av.w};
        float bb[4] = {bv.x, bv.y, bv.z, bv.w};
        #pragma unroll
        for (int a = 0; a < 4; a++)
            #pragma unroll
            for (int b = 0; b < 4; b++)
                acc[a][b] = fmaf(aa[a], bb[b], acc[a][b]);
    }
    float* dst = g_M3 + (size_t)c * NS * NS;
    #pragma unroll
    for (int a = 0; a < 4; a++)
        *(float4*)&dst[(x0 + a) * NS + y0] =
            make_float4(acc[a][0], acc[a][1], acc[a][2], acc[a][3]);
    if (tid == 0) g_S3[c] = g_S1[3 * c] + g_S1[3 * c + 1] + g_S1[3 * c + 2];
}

// ============================================================
// Pass 2: serial matvec over 148 combined chunks (P-layout).
// ============================================================
__global__ void __launch_bounds__(256) pass2_kernel(const int* __restrict__ x,
                                                    const float* __restrict__ priors,
                                                    float* __restrict__ out) {
    __shared__ float alpha[NS];
    __shared__ float part[256];
    __shared__ float anew[NS];
    __shared__ float evec[NS];
    __shared__ float wm2[2];
    int tid = threadIdx.x;
    int i = tid & 63, q = tid >> 6;

    if (tid < NS) {
        float e = priors[tid] - g_lamsum[tid];
        #pragma unroll
        for (int m = 0; m < MD; m++)
            e = fmaf((float)x[m], g_loglam[tid * MD + m], e);
        evec[tid] = e;
    }
    __syncthreads();
    if (tid < NS) {
        float m = evec[tid];
        #pragma unroll
        for (int o = 16; o > 0; o >>= 1)
            m = fmaxf(m, __shfl_xor_sync(0xffffffffu, m, o));
        if ((tid & 31) == 0) wm2[tid >> 5] = m;
    }
    __syncthreads();
    float m0 = fmaxf(wm2[0], wm2[1]);
    if (tid < NS) alpha[tid] = expf(evec[tid] - m0);
    double logscale = (double)m0;
    __syncthreads();

    float buf[2][16];
    #pragma unroll
    for (int r = 0; r < 16; r++)
        buf[0][r] = g_M3[(size_t)(q * 16 + r) * NS + i];
    int pp = 0;
    for (int c = 0; c < NCH3; c++) {
        if (c + 1 < NCH3) {
            #pragma unroll
            for (int r = 0; r < 16; r++)
                buf[pp ^ 1][r] = g_M3[(size_t)(c + 1) * (NS * NS) + (size_t)(q * 16 + r) * NS + i];
        }
        float partial = 0.f;
        #pragma unroll
        for (int r = 0; r < 16; r++)
            partial = fmaf(buf[pp][r], alpha[q * 16 + r], partial);
        part[tid] = partial;
        __syncthreads();
        if (tid < NS) {
            float a4 = part[tid] + part[tid + 64] + part[tid + 128] + part[tid + 192];
            anew[tid] = a4;
            float m = a4;
            #pragma unroll
            for (int o = 16; o > 0; o >>= 1)
                m = fmaxf(m, __shfl_xor_sync(0xffffffffu, m, o));
            if ((tid & 31) == 0) wm2[tid >> 5] = m;
        }
        __syncthreads();
        float s = fmaxf(fmaxf(wm2[0], wm2[1]), 1e-35f);
        if (tid == 0) logscale += (double)g_S3[c] + log((double)s);
        if (tid < NS) alpha[tid] = anew[tid] / s;
        __syncthreads();
        pp ^= 1;
    }

    if (tid == 0) {
        double sum = 0.0;
        for (int k = 0; k < NS; k++) sum += (double)alpha[k];
        double lgam = 0.0;
        for (int b = 0; b < 32; b++) {
            unsigned int cnt = g_hist[b];
            if (cnt) lgam += (double)cnt * lgamma((double)b + 1.0);
        }
        out[0] = (float)(logscale + log(sum) - lgam);
    }
}

// ============================================================
extern "C" void kernel_launch(void* const* d_in, const int* in_sizes, int n_in,
                              void* d_out, int out_size) {
    const int*   x              = (const int*)d_in[0];
    const float* lambdas        = (const float*)d_in[1];
    const float* log_transition = (const float*)d_in[2];
    const float* priors         = (const float*)d_in[3];
    float* out = (float*)d_out;

    setup_kernel<<<1, 256>>>(lambdas, log_transition);
    pass0_kernel<<<T_LEN / 8, 256>>>(x);
    pass1_mma<<<NCH1, 128>>>();
    combine3_kernel<<<NCH3, 256>>>();
    pass2_kernel<<<1, 256>>>(x, priors, out);
}